// round 7
// baseline (speedup 1.0000x reference)
#include <cuda_runtime.h>
#include <cuda_bf16.h>

#define BB 4
#define NN 8192
#define CC 1024
#define SS 16
#define NTOK (BB * NN)       // 32768
#define CH32 32              // scan chunk = 32 tokens
#define NCH32 (NTOK / CH32)  // 1024 global chunks (256 per batch)
#define NCHB (NN / CH32)     // 256 chunks per batch

typedef unsigned long long ull;

// Partial per-token state per c-quarter: 4 x 2MB (L2-resident)
__device__ float g_xstate[4][NTOK * SS];
// Partial 32-token chunk sums per c-quarter
__device__ float g_chsum[4][NCH32 * SS];
// Exclusive per-chunk prefixes (combined, per batch)
__device__ float g_cprefix[NCH32 * SS];

// ---------- packed f32x2 + async helpers ----------
__device__ __forceinline__ ull dup2(float x) {
    ull r;
    unsigned u = __float_as_uint(x);
    asm("mov.b64 %0, {%1, %1};" : "=l"(r) : "r"(u));
    return r;
}
__device__ __forceinline__ void fma2(ull& d, ull a, ull b) {
    asm("fma.rn.f32x2 %0, %1, %2, %0;" : "+l"(d) : "l"(a), "l"(b));
}
__device__ __forceinline__ ull add2(ull a, ull b) {
    ull r;
    asm("add.rn.f32x2 %0, %1, %2;" : "=l"(r) : "l"(a), "l"(b));
    return r;
}
__device__ __forceinline__ unsigned sptr(const void* p) {
    unsigned r;
    asm("{.reg .u64 t; cvta.to.shared.u64 t, %1; cvt.u32.u64 %0, t;}"
        : "=r"(r) : "l"(p));
    return r;
}
__device__ __forceinline__ void cp16(unsigned d, const void* s) {
    asm volatile("cp.async.ca.shared.global [%0], [%1], 16;" :: "r"(d), "l"(s));
}
__device__ __forceinline__ void cp_commit() {
    asm volatile("cp.async.commit_group;");
}

// ================= K1: partial x_state + 32-token chunk sums =================
// Grid = 1024: block = (128-token group) x (256-c quarter). 256 thr = 8 warps.
// 4 iters of 64-c windows; warp w owns 8 c; lane handles tokens l+32k, k=0..3
// -> each broadcast A LDS.128 feeds 8 fma2 (ratio 1:8).
// xs rows padded to 68 words (68%32==4 -> LDS.128 4-phase conflict-free).
// reduce buffer rows stride 10 ull (20 words; starts 20l%32 cover all banks
// in 8-lane groups -> STS/LDS.128 at the 4-phase floor).
#define XSROW 68
#define XSBYTES (128 * XSROW * 4)          // 34816
#define K1_SMEM (8 * 128 * 10 * 8)         // red: 81920 bytes (max region)

__global__ void __launch_bounds__(256, 2) k1_xstate(const float* __restrict__ x,
                                                    const float* __restrict__ A) {
    extern __shared__ char smem_raw[];
    float* xsb[2] = {(float*)smem_raw, (float*)(smem_raw + XSBYTES)};
    ull* Asb[2] = {(ull*)(smem_raw + 2 * XSBYTES),
                   (ull*)(smem_raw + 2 * XSBYTES + 4096)};
    ull* red = (ull*)smem_raw;  // [8 e][128 t][10] — used after compute

    const int tid = threadIdx.x;
    const int w = tid >> 5;
    const int l = tid & 31;
    const int tkb = blockIdx.x >> 2;   // 128-token group
    const int q = blockIdx.x & 3;      // c-quarter
    const long T0 = (long)tkb * 128;
    const int C0 = q * 256;

    auto issue = [&](int it, int buf) {
        const float* xbase = x + T0 * CC + C0 + it * 64;
#pragma unroll
        for (int j = 0; j < 8; j++) {
            int o = tid + j * 256;
            int t = o >> 4, sub = o & 15;
            cp16(sptr(&xsb[buf][t * XSROW + sub * 4]),
                 xbase + (long)t * CC + sub * 4);
        }
        {
            int c = tid >> 2, k = tid & 3;
            cp16(sptr(&Asb[buf][c * 8 + k * 2]),
                 A + (C0 + it * 64 + c) * SS + k * 4);
        }
        cp_commit();
    };

    issue(0, 0);
    issue(1, 1);

    ull acc[4][8];
#pragma unroll
    for (int k = 0; k < 4; k++)
#pragma unroll
        for (int jp = 0; jp < 8; jp++) acc[k][jp] = 0ull;

    for (int it = 0; it < 4; it++) {
        const int buf = it & 1;
        if (it < 3)
            asm volatile("cp.async.wait_group 1;");
        else
            asm volatile("cp.async.wait_group 0;");
        __syncthreads();

        const float* xrow = xsb[buf] + l * XSROW + w * 8;
        const ull* Abase = Asb[buf] + (w * 8) * 8;

#pragma unroll
        for (int cc = 0; cc < 2; cc++) {
            float fx[4][4];
#pragma unroll
            for (int k = 0; k < 4; k++) {
                float4 v = *reinterpret_cast<const float4*>(
                    xrow + k * 32 * XSROW + cc * 4);
                fx[k][0] = v.x; fx[k][1] = v.y; fx[k][2] = v.z; fx[k][3] = v.w;
            }
#pragma unroll
            for (int k4 = 0; k4 < 4; k4++) {
                const int c = cc * 4 + k4;
                ull xd[4];
#pragma unroll
                for (int k = 0; k < 4; k++) xd[k] = dup2(fx[k][k4]);
#pragma unroll
                for (int jq = 0; jq < 4; jq++) {
                    ulonglong2 a2 = *reinterpret_cast<const ulonglong2*>(
                        Abase + c * 8 + jq * 2);
#pragma unroll
                    for (int k = 0; k < 4; k++) {
                        fma2(acc[k][jq * 2], xd[k], a2.x);
                        fma2(acc[k][jq * 2 + 1], xd[k], a2.y);
                    }
                }
            }
        }
        __syncthreads();
        if (it + 2 < 4) issue(it + 2, buf);
    }

    // ---- cross-warp reduce: red[e=w][t][jp], rows stride 10 ull ----
#pragma unroll
    for (int k = 0; k < 4; k++)
#pragma unroll
        for (int p = 0; p < 4; p++) {
            ulonglong2 v;
            v.x = acc[k][p * 2];
            v.y = acc[k][p * 2 + 1];
            *reinterpret_cast<ulonglong2*>(
                &red[(w * 128 + l + 32 * k) * 10 + p * 2]) = v;
        }
    __syncthreads();

    const int t = tid & 127;
    const int sh = tid >> 7;  // state-half: states [sh*8, sh*8+8)
    ulonglong2 s01 = make_ulonglong2(0ull, 0ull);
    ulonglong2 s23 = make_ulonglong2(0ull, 0ull);
#pragma unroll
    for (int e = 0; e < 8; e++) {
        const ull* rp = &red[(e * 128 + t) * 10 + sh * 4];
        ulonglong2 a = *reinterpret_cast<const ulonglong2*>(rp);
        ulonglong2 b = *reinterpret_cast<const ulonglong2*>(rp + 2);
        s01.x = add2(s01.x, a.x);
        s01.y = add2(s01.y, a.y);
        s23.x = add2(s23.x, b.x);
        s23.y = add2(s23.y, b.y);
    }
    {
        ulonglong2* gx = reinterpret_cast<ulonglong2*>(
            &g_xstate[q][(T0 + t) * SS + sh * 8]);
        gx[0] = s01;
        gx[1] = s23;
    }

    // 32-token chunk sums: warp wi covers exactly one 32-token chunk.
    ull v0 = s01.x, v1 = s01.y, v2 = s23.x, v3 = s23.y;
#pragma unroll
    for (int o = 16; o; o >>= 1) {
        v0 = add2(v0, __shfl_xor_sync(0xffffffffu, v0, o));
        v1 = add2(v1, __shfl_xor_sync(0xffffffffu, v1, o));
        v2 = add2(v2, __shfl_xor_sync(0xffffffffu, v2, o));
        v3 = add2(v3, __shfl_xor_sync(0xffffffffu, v3, o));
    }
    if (l == 0) {
        const int wi = tid >> 5;
        const int c32 = wi & 3;    // 32-chunk within the 128-token group
        const int shh = wi >> 2;   // state-half
        ull* gc = reinterpret_cast<ull*>(
            &g_chsum[q][((long)tkb * 4 + c32) * SS + shh * 8]);
        gc[0] = v0; gc[1] = v1; gc[2] = v2; gc[3] = v3;
    }
}

// ================= K2: exclusive scan of 256 chunk sums per batch =================
// Grid = 16 (b x jgroup); 256 threads = one per chunk.
__global__ void __launch_bounds__(256) k2_scan() {
    const int b = blockIdx.x >> 2;
    const int jg = blockIdx.x & 3;
    const int ch = threadIdx.x;  // 0..255
    const long idx = ((long)b * NCHB + ch) * SS + jg * 4;

    float4 s = make_float4(0.f, 0.f, 0.f, 0.f);
#pragma unroll
    for (int qq = 0; qq < 4; qq++) {
        float4 u = *reinterpret_cast<const float4*>(&g_chsum[qq][idx]);
        s.x += u.x; s.y += u.y; s.z += u.z; s.w += u.w;
    }

    __shared__ float4 sc[NCHB];
    sc[ch] = s;
    __syncthreads();
    float4 v = s;
    for (int o = 1; o < NCHB; o <<= 1) {
        float4 u = (ch >= o) ? sc[ch - o] : make_float4(0.f, 0.f, 0.f, 0.f);
        __syncthreads();
        v.x += u.x; v.y += u.y; v.z += u.z; v.w += u.w;
        sc[ch] = v;
        __syncthreads();
    }
    float4 e = make_float4(v.x - s.x, v.y - s.y, v.z - s.z, v.w - s.w);
    *reinterpret_cast<float4*>(&g_cprefix[idx]) = e;
}

// ================= K3: local cumsum + (cumstate @ D) =================
// Grid = 1024: block = one 32-token chunk x full 1024 c. 256 thr, 4 c/thread.
// STG.128 stores; 8 broadcast LDS.128 + 32 fma2 per token per thread.
__global__ void __launch_bounds__(256, 2) k3_out(const float* __restrict__ Dg,
                                                 float* __restrict__ out) {
    __shared__ ull cs_s[CH32][SS + 2];  // dup'd states; 144B rows (16B-aligned)

    const int tid = threadIdx.x;
    const int chg = blockIdx.x;        // global 32-token chunk
    const long T0 = (long)chg * CH32;
    const int w = tid >> 5;
    const int l = tid & 31;

    // D fragment first (independent of cumsum): c = 4*tid .. +3
    const int cbase = tid * 4;
    ulonglong2 dfrag[SS];
#pragma unroll
    for (int j = 0; j < SS; j++)
        dfrag[j] = *reinterpret_cast<const ulonglong2*>(Dg + j * CC + cbase);

    // Warp w: cumsum for states 2w, 2w+1 over 32 tokens (lane = token).
#pragma unroll
    for (int jj = 0; jj < 2; jj++) {
        const int j = w * 2 + jj;
        float v = g_xstate[0][(T0 + l) * SS + j] +
                  g_xstate[1][(T0 + l) * SS + j] +
                  g_xstate[2][(T0 + l) * SS + j] +
                  g_xstate[3][(T0 + l) * SS + j];
#pragma unroll
        for (int o = 1; o < 32; o <<= 1) {
            float u = __shfl_up_sync(0xffffffffu, v, o);
            if (l >= o) v += u;
        }
        v += g_cprefix[chg * SS + j];
        cs_s[l][j] = dup2(v);
    }
    __syncthreads();

    float* op = out + T0 * CC + cbase;
#pragma unroll 4
    for (int tt = 0; tt < CH32; tt++) {
        ull oa = 0ull, ob = 0ull;  // c01 / c23 accumulators
#pragma unroll
        for (int p = 0; p < 8; p++) {
            ulonglong2 c2 =
                *reinterpret_cast<const ulonglong2*>(&cs_s[tt][p * 2]);  // bcast
            fma2(oa, c2.x, dfrag[2 * p].x);
            fma2(ob, c2.x, dfrag[2 * p].y);
            fma2(oa, c2.y, dfrag[2 * p + 1].x);
            fma2(ob, c2.y, dfrag[2 * p + 1].y);
        }
        ulonglong2 r;
        r.x = oa;
        r.y = ob;
        *reinterpret_cast<ulonglong2*>(op + (long)tt * CC) = r;  // STG.128
    }
}

extern "C" void kernel_launch(void* const* d_in, const int* in_sizes, int n_in,
                              void* d_out, int out_size) {
    const float* x = (const float*)d_in[0];
    const float* A = (const float*)d_in[1];
    const float* D = (const float*)d_in[2];
    float* out = (float*)d_out;

    cudaFuncSetAttribute(k1_xstate, cudaFuncAttributeMaxDynamicSharedMemorySize,
                         K1_SMEM);

    k1_xstate<<<(NTOK / 128) * 4, 256, K1_SMEM>>>(x, A);
    k2_scan<<<16, 256>>>();
    k3_out<<<NCH32, 256>>>(D, out);
}